// round 15
// baseline (speedup 1.0000x reference)
#include <cuda_runtime.h>
#include <cuda_bf16.h>
#include <type_traits>

// Problem shape constants (fixed by setup_inputs)
#define B_  2
#define HI  64
#define WI  64
#define DI  32
#define CC  16
#define FF  8
#define HO  128
#define WO  128
#define DO_ 64

// Weight tap repacked as [fg][cg][f_local][4 floats] = 128 floats = 512 B.
#define TAPB 512

typedef unsigned long long u64;

// ---- packed f32x2 helpers (sm_100+; ptxas never emits these from C++) ----
__device__ __forceinline__ u64 fma2(u64 a, u64 b, u64 c) {
    u64 d;
    asm("fma.rn.f32x2 %0, %1, %2, %3;" : "=l"(d) : "l"(a), "l"(b), "l"(c));
    return d;
}
__device__ __forceinline__ u64 add2(u64 a, u64 b) {
    u64 d;
    asm("add.rn.f32x2 %0, %1, %2;" : "=l"(d) : "l"(a), "l"(b));
    return d;
}
__device__ __forceinline__ void ldg128(u64& a, u64& b, const float* p) {
    asm("ld.global.nc.v2.b64 {%0, %1}, [%2];" : "=l"(a), "=l"(b) : "l"(p));
}
__device__ __forceinline__ void lds128(u64& a, u64& b, unsigned addr) {
    asm("ld.shared.v2.b64 {%0, %1}, [%2];" : "=l"(a), "=l"(b) : "r"(addr));
}
__device__ __forceinline__ u64 pack2(float x) {
    u64 d;
    asm("mov.b64 %0, {%1, %1};" : "=l"(d) : "f"(x));
    return d;
}
__device__ __forceinline__ float lo32(u64 a) { return __uint_as_float((unsigned)a); }
__device__ __forceinline__ float hi32(u64 a) { return __uint_as_float((unsigned)(a >> 32)); }

// Load one depth-row slice for this lane: 4 floats = 2 u64 (16 B), or default.
__device__ __forceinline__ void load_row4(u64 r[2], const float* p, bool ok, u64 dv2) {
    if (ok) ldg128(r[0], r[1], p);
    else    { r[0] = dv2; r[1] = dv2; }
}

// One input pixel's depth taps. Lane owns 4 channels (cg), 4 filters (fg),
// 4 depth slabs (g: s = half*16 + 4g + j).
// MODD=true : taps kd=0 & kd=2. Slab j: row (r0+j) w/ kd0, row (r0+j-1) w/ kd2
//             -> 5-row window rows[t] = r0-1+t.
// MODD=false: tap kd=1. Slab j: row (r0+j) -> 4-row window.
// wbhw = smem weight base for (kh,kw,kd=0) incl. lane's (fg,cg) offset.
template<bool MODD>
__device__ __forceinline__ void pixel_taps(const float* __restrict__ irow,
                                           unsigned wbhw, int r0, u64 dv2,
                                           u64 (*acc)[4])
{
    if (MODD) {
        u64 rows[5][2];
        const float* p = irow + (long)(r0 - 1) * CC;
        #pragma unroll
        for (int t = 0; t < 5; t++)
            load_row4(rows[t], p + t * CC, (unsigned)(r0 - 1 + t) < DI, dv2);
        const unsigned wb0 = wbhw;                // kd = 0 weights
        const unsigned wb2 = wbhw + 2 * TAPB;     // kd = 2 weights
        #pragma unroll
        for (int f = 0; f < 4; f++) {
            u64 w0, w1, x0, x1;
            lds128(w0, w1, wb0 + f * 16);
            lds128(x0, x1, wb2 + f * 16);
            #pragma unroll
            for (int j = 0; j < 4; j++) {
                acc[f][j] = fma2(rows[j + 1][0], w0, acc[f][j]);
                acc[f][j] = fma2(rows[j + 1][1], w1, acc[f][j]);
                acc[f][j] = fma2(rows[j][0],     x0, acc[f][j]);
                acc[f][j] = fma2(rows[j][1],     x1, acc[f][j]);
            }
        }
    } else {
        u64 rows[4][2];
        const float* p = irow + (long)r0 * CC;
        #pragma unroll
        for (int t = 0; t < 4; t++)
            load_row4(rows[t], p + t * CC, (unsigned)(r0 + t) < DI, dv2);
        const unsigned wb1 = wbhw + TAPB;         // kd = 1 weights
        #pragma unroll
        for (int f = 0; f < 4; f++) {
            u64 w0, w1;
            lds128(w0, w1, wb1 + f * 16);
            #pragma unroll
            for (int j = 0; j < 4; j++) {
                acc[f][j] = fma2(rows[j][0], w0, acc[f][j]);
                acc[f][j] = fma2(rows[j][1], w1, acc[f][j]);
            }
        }
    }
}

// Block: 256 threads = 8 warps = 2 wo x 2 par x 2 half. Grid (WO/2, HO, B).
// Warp handles 16 of the 32 depth slabs of its (wo,par) column (half picks
// which 16). Lane = g*8 + fg*4 + cg: cg owns channels [cg*4, cg*4+4), fg owns
// filters [fg*4, fg*4+4), g owns slabs half*16 + 4g .. +3. Valid taps are
// precomputed from the three warp-uniform parity bits. Channel reduction is a
// 4-lane reduce-scatter (2 shfl stages); lane keeps slab j == cg.
__global__ __launch_bounds__(256, 3)
void sparse_conv3d_transpose_kernel(const float* __restrict__ images,
                                    const int*   __restrict__ base_plane,
                                    const float* __restrict__ kernel,
                                    const float* __restrict__ defv,
                                    float*       __restrict__ out)
{
    __shared__ __align__(16) float sw[27 * 128];   // 13824 B, repacked taps
    // repack [tap][f][c] -> [tap][fg][cg][f_local][q]
    for (int i = threadIdx.x; i < 27 * FF * CC; i += 256) {
        const int tap = i >> 7;
        const int f   = (i >> 4) & 7;
        const int c   = i & 15;
        const int dst = tap * 128 + (f >> 2) * 64 + (c >> 2) * 16 + (f & 3) * 4 + (c & 3);
        sw[dst] = kernel[i];
    }
    __syncthreads();

    const int b    = blockIdx.z;
    const int ho   = blockIdx.y;
    const int warp = threadIdx.x >> 5;
    const int lane = threadIdx.x & 31;
    const int wo   = (blockIdx.x << 1) + (warp >> 2);
    const int par  = (warp >> 1) & 1;
    const int half = warp & 1;
    const int cg   = lane & 3;
    const int fg   = (lane >> 2) & 1;
    const int g    = lane >> 3;

    const u64 dv2 = pack2(*defv);
    const int bpv = __ldg(base_plane + (b * HO + ho) * WO + wo);
    const int m   = bpv + par;

    // swbase folds in this lane's (fg, cg) weight offset.
    const unsigned swbase = (unsigned)__cvta_generic_to_shared(sw)
                          + (unsigned)(fg * 256 + cg * 64);

    u64 acc[4][4];   // [f-local][j] : partials over this lane's 4 channels
    #pragma unroll
    for (int f = 0; f < 4; f++)
        #pragma unroll
        for (int j = 0; j < 4; j++) acc[f][j] = 0ull;

    // --- precompute valid spatial taps (warp-uniform, <=2 each) ---
    int hi0, hi1 = 0, nh;
    unsigned wbh0, wbh1 = 0;                       // kh * 9 * TAPB
    if (ho & 1) {
        if (ho == HO - 1) { nh = 1; hi0 = (ho - 1) >> 1; wbh0 = 2u * 9 * TAPB; }
        else { nh = 2; hi0 = (ho + 1) >> 1; wbh0 = 0;
               hi1 = (ho - 1) >> 1; wbh1 = 2u * 9 * TAPB; }
    } else { nh = 1; hi0 = ho >> 1; wbh0 = 1u * 9 * TAPB; }

    int wi0, wi1 = 0, nw;
    unsigned wbw0, wbw1 = 0;                       // kw * 3 * TAPB
    if (wo & 1) {
        if (wo == WO - 1) { nw = 1; wi0 = (wo - 1) >> 1; wbw0 = 2u * 3 * TAPB; }
        else { nw = 2; wi0 = (wo + 1) >> 1; wbw0 = 0;
               wi1 = (wo - 1) >> 1; wbw1 = 2u * 3 * TAPB; }
    } else { nw = 1; wi0 = wo >> 1; wbw0 = 1u * 3 * TAPB; }

    auto spatial = [&](auto modd_c) {
        constexpr bool MODD = decltype(modd_c)::value;
        const int off = MODD ? ((m + 1) >> 1) : (m >> 1);
        #pragma unroll 1
        for (int a = 0; a < nh; a++) {
            const int hi       = a ? hi1 : hi0;
            const unsigned wbh = a ? wbh1 : wbh0;
            const int bprow    = (b * HO + (hi << 1)) * WO;
            const float* hrow  = images + (size_t)((b * HI + hi) * WI) * DI * CC;
            #pragma unroll 1
            for (int c = 0; c < nw; c++) {
                const int wi       = c ? wi1 : wi0;
                const unsigned wbw = c ? wbw1 : wbw0;
                const int bpg = __ldg(base_plane + bprow + (wi << 1)) >> 1;
                const float* irow = hrow + (size_t)wi * DI * CC + cg * 4;
                const int r0 = half * 16 + 4 * g + off - bpg;
                pixel_taps<MODD>(irow, swbase + wbh + wbw, r0, dv2, acc);
            }
        }
    };

    if (m & 1) spatial(std::integral_constant<bool, true>{});
    else       spatial(std::integral_constant<bool, false>{});

    // 4-lane reduce-scatter over the cg group: lane ends with the full
    // 16-channel sum of slab j == cg for its 4 filters.
    const bool b1 = (cg & 2) != 0;
    const bool b0 = (cg & 1) != 0;
    float r[4];
    #pragma unroll
    for (int f = 0; f < 4; f++) {
        u64 k0 = b1 ? acc[f][2] : acc[f][0];   // elements this lane keeps
        u64 k1 = b1 ? acc[f][3] : acc[f][1];
        u64 g0 = b1 ? acc[f][0] : acc[f][2];   // elements the partner keeps
        u64 g1 = b1 ? acc[f][1] : acc[f][3];
        k0 = add2(k0, __shfl_xor_sync(0xffffffffu, g0, 2));
        k1 = add2(k1, __shfl_xor_sync(0xffffffffu, g1, 2));
        u64 k  = b0 ? k1 : k0;
        u64 gv = b0 ? k0 : k1;
        k = add2(k, __shfl_xor_sync(0xffffffffu, gv, 1));
        r[f] = lo32(k) + hi32(k);
    }

    const size_t obase = ((size_t)((b * HO + ho) * WO + wo)) * DO_;
    const int dout = 2 * (half * 16 + 4 * g + cg) + par;
    *(float4*)(out + (obase + dout) * FF + fg * 4) = make_float4(r[0], r[1], r[2], r[3]);
}

extern "C" void kernel_launch(void* const* d_in, const int* in_sizes, int n_in,
                              void* d_out, int out_size)
{
    const float* images     = (const float*)d_in[0];   // [2,64,64,32,16] f32
    const int*   base_plane = (const int*)  d_in[1];   // [2,128,128,1] i32
    const float* kern       = (const float*)d_in[2];   // [3,3,3,8,16] f32
    const float* defv       = (const float*)d_in[3];   // scalar f32 (zero)
    float*       out        = (float*)d_out;           // [2,128,128,64,8] f32

    dim3 grid(WO / 2, HO, B_);
    sparse_conv3d_transpose_kernel<<<grid, 256>>>(images, base_plane, kern, defv, out);
}

// round 16
// speedup vs baseline: 1.2013x; 1.2013x over previous
#include <cuda_runtime.h>
#include <cuda_bf16.h>
#include <type_traits>

// Problem shape constants (fixed by setup_inputs)
#define B_  2
#define HI  64
#define WI  64
#define DI  32
#define CC  16
#define FF  8
#define HO  128
#define WO  128
#define DO_ 64

// Per-kd weight block: 8 filters * 16 ch * 4B = 512 B,
// repacked as [f_local][pass][fg][cg][4 floats].
#define TAPB 512

typedef unsigned long long u64;

// ---- packed f32x2 helpers (sm_100+; ptxas never emits these from C++) ----
__device__ __forceinline__ u64 fma2(u64 a, u64 b, u64 c) {
    u64 d;
    asm("fma.rn.f32x2 %0, %1, %2, %3;" : "=l"(d) : "l"(a), "l"(b), "l"(c));
    return d;
}
__device__ __forceinline__ u64 add2(u64 a, u64 b) {
    u64 d;
    asm("add.rn.f32x2 %0, %1, %2;" : "=l"(d) : "l"(a), "l"(b));
    return d;
}
__device__ __forceinline__ void ldg128(u64& a, u64& b, const float* p) {
    asm("ld.global.nc.v2.b64 {%0, %1}, [%2];" : "=l"(a), "=l"(b) : "l"(p));
}
__device__ __forceinline__ void lds128(u64& a, u64& b, unsigned addr) {
    asm("ld.shared.v2.b64 {%0, %1}, [%2];" : "=l"(a), "=l"(b) : "r"(addr));
}
__device__ __forceinline__ u64 pack2(float x) {
    u64 d;
    asm("mov.b64 %0, {%1, %1};" : "=l"(d) : "f"(x));
    return d;
}
__device__ __forceinline__ float lo32(u64 a) { return __uint_as_float((unsigned)a); }
__device__ __forceinline__ float hi32(u64 a) { return __uint_as_float((unsigned)(a >> 32)); }

// Load one depth-row quad for this lane: 4 floats = 2 u64 (16 B), or default.
__device__ __forceinline__ void load_row4(u64 r[2], const float* p, bool ok, u64 dv2) {
    if (ok) ldg128(r[0], r[1], p);
    else    { r[0] = dv2; r[1] = dv2; }
}

// One input pixel's depth taps. Lane owns 8 channels (cg half), 4 filters (fg),
// 4 depth slabs (g: s = 4g+j). The 8 channels are processed as TWO sequential
// 4-channel passes so the row window is only rows[5][2] (10 u64) while acc
// accumulates across passes.
// MODD=true : taps kd=0 & kd=2. Slab j: row (r0+j) w/ kd0, row (r0+j-1) w/ kd2
//             -> 5-row window rows[t] = r0-1+t.
// MODD=false: tap kd=1. Slab j: row (r0+j) -> 4-row window.
// irow includes the lane's cg*8 channel offset; wbhw = smem base for
// (kh,kw,kd=0) incl. the lane's (fg,cg) offset.
template<bool MODD>
__device__ __forceinline__ void pixel_taps(const float* __restrict__ irow,
                                           unsigned wbhw, int r0, u64 dv2,
                                           u64 (*acc)[4])
{
    #pragma unroll
    for (int pass = 0; pass < 2; pass++) {
        const float* ip = irow + pass * 4;
        const unsigned wp = wbhw + pass * 64;
        if (MODD) {
            u64 rows[5][2];
            const float* p = ip + (long)(r0 - 1) * CC;
            #pragma unroll
            for (int t = 0; t < 5; t++)
                load_row4(rows[t], p + t * CC, (unsigned)(r0 - 1 + t) < DI, dv2);
            const unsigned wb0 = wp;                // kd = 0 weights
            const unsigned wb2 = wp + 2 * TAPB;     // kd = 2 weights
            #pragma unroll
            for (int f = 0; f < 4; f++) {
                u64 w0, w1, x0, x1;
                lds128(w0, w1, wb0 + f * 128);
                lds128(x0, x1, wb2 + f * 128);
                #pragma unroll
                for (int j = 0; j < 4; j++) {
                    acc[f][j] = fma2(rows[j + 1][0], w0, acc[f][j]);
                    acc[f][j] = fma2(rows[j + 1][1], w1, acc[f][j]);
                    acc[f][j] = fma2(rows[j][0],     x0, acc[f][j]);
                    acc[f][j] = fma2(rows[j][1],     x1, acc[f][j]);
                }
            }
        } else {
            u64 rows[4][2];
            const float* p = ip + (long)r0 * CC;
            #pragma unroll
            for (int t = 0; t < 4; t++)
                load_row4(rows[t], p + t * CC, (unsigned)(r0 + t) < DI, dv2);
            const unsigned wb1 = wp + TAPB;         // kd = 1 weights
            #pragma unroll
            for (int f = 0; f < 4; f++) {
                u64 w0, w1;
                lds128(w0, w1, wb1 + f * 128);
                #pragma unroll
                for (int j = 0; j < 4; j++) {
                    acc[f][j] = fma2(rows[j][0], w0, acc[f][j]);
                    acc[f][j] = fma2(rows[j][1], w1, acc[f][j]);
                }
            }
        }
    }
}

// Block: 256 threads = 8 warps. Warp w: wo = blockIdx.x*4 + w/2, parity = w&1
// (full 32-slab column per warp — per-warp overhead amortized). Lane =
// g*4 + fg*2 + cg: cg owns channels [cg*8, cg*8+8), fg owns filters
// [fg*4, fg*4+4), g owns depth slabs 4g..4g+3 (douts 2s+par). Valid taps are
// precomputed from the three warp-uniform parity bits. Channel reduction is a
// single shfl_xor(1); afterwards lane keeps slabs j in {2cg, 2cg+1}.
__global__ __launch_bounds__(256, 3)
void sparse_conv3d_transpose_kernel(const float* __restrict__ images,
                                    const int*   __restrict__ base_plane,
                                    const float* __restrict__ kernel,
                                    const float* __restrict__ defv,
                                    float*       __restrict__ out)
{
    __shared__ __align__(16) float sw[27 * 128];   // 13824 B, repacked taps
    // repack [tap][f][c] -> [tap][f&3][pass=(c>>2)&1][fg=f>>2][cg=c>>3][c&3]
    // so the 4 concurrent (fg,cg) lane addresses per lds128 are contiguous
    // 64 B (banks 0-15, conflict-free).
    for (int i = threadIdx.x; i < 27 * FF * CC; i += 256) {
        const int tap = i >> 7;
        const int f   = (i >> 4) & 7;
        const int c   = i & 15;
        const int dst = tap * 128 + (f & 3) * 32 + ((c >> 2) & 1) * 16
                      + (f >> 2) * 8 + (c >> 3) * 4 + (c & 3);
        sw[dst] = kernel[i];
    }
    __syncthreads();

    const int b    = blockIdx.z;
    const int ho   = blockIdx.y;
    const int warp = threadIdx.x >> 5;
    const int lane = threadIdx.x & 31;
    const int wo   = (blockIdx.x << 2) + (warp >> 1);
    const int par  = warp & 1;
    const int cg   = lane & 1;
    const int fg   = (lane >> 1) & 1;
    const int g    = lane >> 2;

    const u64 dv2 = pack2(*defv);
    const int bpv = __ldg(base_plane + (b * HO + ho) * WO + wo);
    const int m   = bpv + par;

    // swbase folds in this lane's (fg, cg) weight offset.
    const unsigned swbase = (unsigned)__cvta_generic_to_shared(sw)
                          + (unsigned)(fg * 8 + cg * 4) * 4;

    u64 acc[4][4];   // [f-local][j] : partials over this lane's 8 channels
    #pragma unroll
    for (int f = 0; f < 4; f++)
        #pragma unroll
        for (int j = 0; j < 4; j++) acc[f][j] = 0ull;

    // --- precompute valid spatial taps (warp-uniform, <=2 each) ---
    int hi0, hi1 = 0, nh;
    unsigned wbh0, wbh1 = 0;                       // kh * 9 * TAPB
    if (ho & 1) {
        if (ho == HO - 1) { nh = 1; hi0 = (ho - 1) >> 1; wbh0 = 2u * 9 * TAPB; }
        else { nh = 2; hi0 = (ho + 1) >> 1; wbh0 = 0;
               hi1 = (ho - 1) >> 1; wbh1 = 2u * 9 * TAPB; }
    } else { nh = 1; hi0 = ho >> 1; wbh0 = 1u * 9 * TAPB; }

    int wi0, wi1 = 0, nw;
    unsigned wbw0, wbw1 = 0;                       // kw * 3 * TAPB
    if (wo & 1) {
        if (wo == WO - 1) { nw = 1; wi0 = (wo - 1) >> 1; wbw0 = 2u * 3 * TAPB; }
        else { nw = 2; wi0 = (wo + 1) >> 1; wbw0 = 0;
               wi1 = (wo - 1) >> 1; wbw1 = 2u * 3 * TAPB; }
    } else { nw = 1; wi0 = wo >> 1; wbw0 = 1u * 3 * TAPB; }

    auto spatial = [&](auto modd_c) {
        constexpr bool MODD = decltype(modd_c)::value;
        const int off = MODD ? ((m + 1) >> 1) : (m >> 1);
        #pragma unroll 1
        for (int a = 0; a < nh; a++) {
            const int hi       = a ? hi1 : hi0;
            const unsigned wbh = a ? wbh1 : wbh0;
            const int bprow    = (b * HO + (hi << 1)) * WO;
            const float* hrow  = images + (size_t)((b * HI + hi) * WI) * DI * CC;
            #pragma unroll 1
            for (int c = 0; c < nw; c++) {
                const int wi       = c ? wi1 : wi0;
                const unsigned wbw = c ? wbw1 : wbw0;
                const int bpg = __ldg(base_plane + bprow + (wi << 1)) >> 1;
                const float* irow = hrow + (size_t)wi * DI * CC + cg * 8;
                const int r0 = 4 * g + off - bpg;
                pixel_taps<MODD>(irow, swbase + wbh + wbw, r0, dv2, acc);
            }
        }
    };

    if (m & 1) spatial(std::integral_constant<bool, true>{});
    else       spatial(std::integral_constant<bool, false>{});

    // Reduce across the cg pair (other 8 channels); lane keeps slabs 2cg,2cg+1.
    #pragma unroll
    for (int f = 0; f < 4; f++)
        #pragma unroll
        for (int j = 0; j < 4; j++)
            acc[f][j] = add2(acc[f][j], __shfl_xor_sync(0xffffffffu, acc[f][j], 1));

    const size_t obase = ((size_t)((b * HO + ho) * WO + wo)) * DO_;
    #pragma unroll
    for (int jj = 0; jj < 2; jj++) {
        const int j    = 2 * cg + jj;
        const int dout = 2 * (4 * g + j) + par;
        float4 v;
        v.x = lo32(acc[0][j]) + hi32(acc[0][j]);
        v.y = lo32(acc[1][j]) + hi32(acc[1][j]);
        v.z = lo32(acc[2][j]) + hi32(acc[2][j]);
        v.w = lo32(acc[3][j]) + hi32(acc[3][j]);
        *(float4*)(out + (obase + dout) * FF + fg * 4) = v;
    }
}

extern "C" void kernel_launch(void* const* d_in, const int* in_sizes, int n_in,
                              void* d_out, int out_size)
{
    const float* images     = (const float*)d_in[0];   // [2,64,64,32,16] f32
    const int*   base_plane = (const int*)  d_in[1];   // [2,128,128,1] i32
    const float* kern       = (const float*)d_in[2];   // [3,3,3,8,16] f32
    const float* defv       = (const float*)d_in[3];   // scalar f32 (zero)
    float*       out        = (float*)d_out;           // [2,128,128,64,8] f32

    dim3 grid(WO / 4, HO, B_);
    sparse_conv3d_transpose_kernel<<<grid, 256>>>(images, base_plane, kern, defv, out);
}

// round 17
// speedup vs baseline: 1.8255x; 1.5197x over previous
#include <cuda_runtime.h>
#include <cuda_bf16.h>
#include <type_traits>

// Problem shape constants (fixed by setup_inputs)
#define B_  2
#define HI  64
#define WI  64
#define DI  32
#define CC  16
#define FF  8
#define HO  128
#define WO  128
#define DO_ 64

// Per-(kh,kw,kd) weight block, repacked: [chl(8)][cg(2)][fpair(4) u64] = 512 B.
#define TAPB 512

typedef unsigned long long u64;

// ---- packed f32x2 helpers (sm_100+; ptxas never emits these from C++) ----
__device__ __forceinline__ u64 fma2(u64 a, u64 b, u64 c) {
    u64 d;
    asm("fma.rn.f32x2 %0, %1, %2, %3;" : "=l"(d) : "l"(a), "l"(b), "l"(c));
    return d;
}
__device__ __forceinline__ u64 add2(u64 a, u64 b) {
    u64 d;
    asm("add.rn.f32x2 %0, %1, %2;" : "=l"(d) : "l"(a), "l"(b));
    return d;
}
__device__ __forceinline__ void lds128(u64& a, u64& b, unsigned addr) {
    asm("ld.shared.v2.b64 {%0, %1}, [%2];" : "=l"(a), "=l"(b) : "r"(addr));
}
__device__ __forceinline__ u64 pack2(float x) {
    u64 d;
    asm("mov.b64 %0, {%1, %1};" : "=l"(d) : "f"(x));
    return d;
}
__device__ __forceinline__ float lo32(u64 a) { return __uint_as_float((unsigned)a); }
__device__ __forceinline__ float hi32(u64 a) { return __uint_as_float((unsigned)(a >> 32)); }

// One input pixel, BOTH parities, all kd taps, from a shared 3-row window.
// Lane owns 8 channels (cg) and 2 depth slabs (j in {0,1}, s = 2*d16 + j).
// accA = odd-type parity (rows[j+1]*Wkd0 + rows[j]*Wkd2),
// accB = even-type parity (rows[j+EO]*Wkd1).  EO = bpv&1 (warp-uniform).
// acc u64 = packed {f, f+1} filter pair; channel sums fold in-register.
template<bool EO>
__device__ __forceinline__ void pixel_all(const float* __restrict__ irow,
                                          unsigned wb, int r, float4 dv4,
                                          u64 (*accA)[4], u64 (*accB)[4])
{
    float4 row[3][2];
    #pragma unroll
    for (int t = 0; t < 3; t++) {
        if ((unsigned)(r + t) < DI) {
            const float4* p = (const float4*)(irow + (long)(r + t) * CC);
            row[t][0] = p[0]; row[t][1] = p[1];
        } else { row[t][0] = dv4; row[t][1] = dv4; }
    }
    #pragma unroll
    for (int h = 0; h < 2; h++) {
        #pragma unroll
        for (int q = 0; q < 4; q++) {
            const int chl = h * 4 + q;
            const float e0 = (q==0)?row[0][h].x:(q==1)?row[0][h].y:(q==2)?row[0][h].z:row[0][h].w;
            const float e1 = (q==0)?row[1][h].x:(q==1)?row[1][h].y:(q==2)?row[1][h].z:row[1][h].w;
            const float e2 = (q==0)?row[2][h].x:(q==1)?row[2][h].y:(q==2)?row[2][h].z:row[2][h].w;
            const u64 s0 = pack2(e0), s1 = pack2(e1), s2 = pack2(e2);
            const unsigned wc = wb + chl * 64;
            u64 wa, wb2, wc2, wd;
            // kd = 0 : odd-type, rows[j+1]
            lds128(wa, wb2, wc);
            lds128(wc2, wd, wc + 16);
            accA[0][0] = fma2(s1, wa,  accA[0][0]);
            accA[0][1] = fma2(s1, wb2, accA[0][1]);
            accA[0][2] = fma2(s1, wc2, accA[0][2]);
            accA[0][3] = fma2(s1, wd,  accA[0][3]);
            accA[1][0] = fma2(s2, wa,  accA[1][0]);
            accA[1][1] = fma2(s2, wb2, accA[1][1]);
            accA[1][2] = fma2(s2, wc2, accA[1][2]);
            accA[1][3] = fma2(s2, wd,  accA[1][3]);
            // kd = 2 : odd-type, rows[j]
            lds128(wa, wb2, wc + 2 * TAPB);
            lds128(wc2, wd, wc + 2 * TAPB + 16);
            accA[0][0] = fma2(s0, wa,  accA[0][0]);
            accA[0][1] = fma2(s0, wb2, accA[0][1]);
            accA[0][2] = fma2(s0, wc2, accA[0][2]);
            accA[0][3] = fma2(s0, wd,  accA[0][3]);
            accA[1][0] = fma2(s1, wa,  accA[1][0]);
            accA[1][1] = fma2(s1, wb2, accA[1][1]);
            accA[1][2] = fma2(s1, wc2, accA[1][2]);
            accA[1][3] = fma2(s1, wd,  accA[1][3]);
            // kd = 1 : even-type, rows[j+EO]
            lds128(wa, wb2, wc + TAPB);
            lds128(wc2, wd, wc + TAPB + 16);
            const u64 t0 = EO ? s1 : s0;
            const u64 t1 = EO ? s2 : s1;
            accB[0][0] = fma2(t0, wa,  accB[0][0]);
            accB[0][1] = fma2(t0, wb2, accB[0][1]);
            accB[0][2] = fma2(t0, wc2, accB[0][2]);
            accB[0][3] = fma2(t0, wd,  accB[0][3]);
            accB[1][0] = fma2(t1, wa,  accB[1][0]);
            accB[1][1] = fma2(t1, wb2, accB[1][1]);
            accB[1][2] = fma2(t1, wc2, accB[1][2]);
            accB[1][3] = fma2(t1, wd,  accB[1][3]);
        }
    }
}

// Block: 256 threads = 8 warps. Warp w handles wo = blockIdx.x*8 + w, BOTH
// parities (identical instruction stream per warp — perfectly balanced).
// Lane = d16*2 + cg: cg owns channels [cg*8, cg*8+8), d16 owns slabs
// s = 2*d16 + j, j in {0,1}. The 3-row window rows[r..r+2] with
// r = 2*d16 + (bpv>>1) - bpg serves all three kd taps of both parities.
__global__ __launch_bounds__(256, 3)
void sparse_conv3d_transpose_kernel(const float* __restrict__ images,
                                    const int*   __restrict__ base_plane,
                                    const float* __restrict__ kernel,
                                    const float* __restrict__ defv,
                                    float*       __restrict__ out)
{
    __shared__ __align__(16) float sw[27 * 128];   // 13824 B
    // repack [tap][f][c] -> [tap][chl=c&7][cg=c>>3][fpair=f>>1][half=f&1]
    for (int i = threadIdx.x; i < 27 * FF * CC; i += 256) {
        const int tap = i >> 7;
        const int f   = (i >> 4) & 7;
        const int c   = i & 15;
        const int dst = tap * 128 + (c & 7) * 16 + (c >> 3) * 8 + (f >> 1) * 2 + (f & 1);
        sw[dst] = kernel[i];
    }
    __syncthreads();

    const int b    = blockIdx.z;
    const int ho   = blockIdx.y;
    const int warp = threadIdx.x >> 5;
    const int lane = threadIdx.x & 31;
    const int wo   = (blockIdx.x << 3) + warp;
    const int cg   = lane & 1;
    const int d16  = lane >> 1;

    const float dv = *defv;
    const float4 dv4 = make_float4(dv, dv, dv, dv);
    const int bpv = __ldg(base_plane + (b * HO + ho) * WO + wo);
    const int eo  = bpv & 1;          // even-type parity index; odd-type = 1-eo

    const unsigned swbase = (unsigned)__cvta_generic_to_shared(sw) + (unsigned)(cg * 32);

    u64 accA[2][4], accB[2][4];       // [j][fpair] packed filter pairs
    #pragma unroll
    for (int j = 0; j < 2; j++)
        #pragma unroll
        for (int p = 0; p < 4; p++) { accA[j][p] = 0ull; accB[j][p] = 0ull; }

    // --- precompute valid spatial taps (warp-uniform, <=2 each) ---
    int hi0, hi1 = 0, nh;
    unsigned wbh0, wbh1 = 0;                       // kh * 9 * TAPB
    if (ho & 1) {
        if (ho == HO - 1) { nh = 1; hi0 = (ho - 1) >> 1; wbh0 = 2u * 9 * TAPB; }
        else { nh = 2; hi0 = (ho + 1) >> 1; wbh0 = 0;
               hi1 = (ho - 1) >> 1; wbh1 = 2u * 9 * TAPB; }
    } else { nh = 1; hi0 = ho >> 1; wbh0 = 1u * 9 * TAPB; }

    int wi0, wi1 = 0, nw;
    unsigned wbw0, wbw1 = 0;                       // kw * 3 * TAPB
    if (wo & 1) {
        if (wo == WO - 1) { nw = 1; wi0 = (wo - 1) >> 1; wbw0 = 2u * 3 * TAPB; }
        else { nw = 2; wi0 = (wo + 1) >> 1; wbw0 = 0;
               wi1 = (wo - 1) >> 1; wbw1 = 2u * 3 * TAPB; }
    } else { nw = 1; wi0 = wo >> 1; wbw0 = 1u * 3 * TAPB; }

    const int rbase = 2 * d16 + (bpv >> 1);

    auto spatial = [&](auto eo_c) {
        constexpr bool EOT = decltype(eo_c)::value;
        #pragma unroll 1
        for (int a = 0; a < nh; a++) {
            const int hi       = a ? hi1 : hi0;
            const unsigned wbh = a ? wbh1 : wbh0;
            const int bprow    = (b * HO + (hi << 1)) * WO;
            const float* hrow  = images + (size_t)((b * HI + hi) * WI) * DI * CC;
            #pragma unroll 1
            for (int c = 0; c < nw; c++) {
                const int wi       = c ? wi1 : wi0;
                const unsigned wbw = c ? wbw1 : wbw0;
                const int bpg = __ldg(base_plane + bprow + (wi << 1)) >> 1;
                const float* irow = hrow + (size_t)wi * DI * CC + cg * 8;
                pixel_all<EOT>(irow, swbase + wbh + wbw, rbase - bpg, dv4, accA, accB);
            }
        }
    };

    if (eo) spatial(std::integral_constant<bool, true>{});
    else    spatial(std::integral_constant<bool, false>{});

    // Reduce across the cg pair (other 8 channels); lane keeps slab j == cg.
    #pragma unroll
    for (int j = 0; j < 2; j++)
        #pragma unroll
        for (int p = 0; p < 4; p++) {
            accA[j][p] = add2(accA[j][p], __shfl_xor_sync(0xffffffffu, accA[j][p], 1));
            accB[j][p] = add2(accB[j][p], __shfl_xor_sync(0xffffffffu, accB[j][p], 1));
        }

    const size_t obase = ((size_t)((b * HO + ho) * WO + wo)) * DO_;
    const int s = 2 * d16 + cg;                     // kept slab (== lane)
    {   // odd-type parity output (par = 1-eo)
        float* op = out + (obase + (2 * s + (1 - eo))) * FF;
        *(float4*)(op)     = make_float4(lo32(accA[cg][0]), hi32(accA[cg][0]),
                                         lo32(accA[cg][1]), hi32(accA[cg][1]));
        *(float4*)(op + 4) = make_float4(lo32(accA[cg][2]), hi32(accA[cg][2]),
                                         lo32(accA[cg][3]), hi32(accA[cg][3]));
    }
    {   // even-type parity output (par = eo)
        float* op = out + (obase + (2 * s + eo)) * FF;
        *(float4*)(op)     = make_float4(lo32(accB[cg][0]), hi32(accB[cg][0]),
                                         lo32(accB[cg][1]), hi32(accB[cg][1]));
        *(float4*)(op + 4) = make_float4(lo32(accB[cg][2]), hi32(accB[cg][2]),
                                         lo32(accB[cg][3]), hi32(accB[cg][3]));
    }
}

extern "C" void kernel_launch(void* const* d_in, const int* in_sizes, int n_in,
                              void* d_out, int out_size)
{
    const float* images     = (const float*)d_in[0];   // [2,64,64,32,16] f32
    const int*   base_plane = (const int*)  d_in[1];   // [2,128,128,1] i32
    const float* kern       = (const float*)d_in[2];   // [3,3,3,8,16] f32
    const float* defv       = (const float*)d_in[3];   // scalar f32 (zero)
    float*       out        = (float*)d_out;           // [2,128,128,64,8] f32

    dim3 grid(WO / 8, HO, B_);
    sparse_conv3d_transpose_kernel<<<grid, 256>>>(images, base_plane, kern, defv, out);
}